// round 12
// baseline (speedup 1.0000x reference)
#include <cuda_runtime.h>
#include <cuda_fp16.h>
#include <math.h>
#include <stdint.h>

// ---------------- problem constants ----------------
#define HIDDEN   768
#define MLPH     3072
#define HEADS    12
#define HEAD_DIM 64
#define BATCH    16
#define SEQ      1024
#define MTOK     (BATCH * SEQ)

// ---------------- scratch ----------------
__device__ __align__(16) __half g_xn  [(size_t)MTOK * HIDDEN];
__device__ __align__(16) __half g_qkv [(size_t)3 * MTOK * HIDDEN];
__device__ __align__(16) __half g_attn[(size_t)MTOK * HIDDEN];
__device__ __align__(16) float  g_x1  [(size_t)MTOK * HIDDEN];
__device__ __align__(16) __half g_h   [(size_t)MTOK * MLPH];
__device__ __align__(16) __half g_w1t [(size_t)MLPH * HIDDEN];
__device__ __align__(16) __half g_w2t [(size_t)HIDDEN * MLPH];
__device__ __align__(16) __half g_wqkv[(size_t)3 * HIDDEN * HIDDEN];
__device__ __align__(16) __half g_wo  [(size_t)HIDDEN * HIDDEN];

// ---------------- helpers ----------------
__device__ __forceinline__ uint32_t smem_u32(const void* p) {
    uint32_t a;
    asm("{ .reg .u64 t; cvta.to.shared.u64 t, %1; cvt.u32.u64 %0, t; }" : "=r"(a) : "l"(p));
    return a;
}
__device__ __forceinline__ void ldsm4(uint32_t* r, uint32_t addr) {
    asm volatile("ldmatrix.sync.aligned.m8n8.x4.shared.b16 {%0,%1,%2,%3}, [%4];"
                 : "=r"(r[0]), "=r"(r[1]), "=r"(r[2]), "=r"(r[3]) : "r"(addr));
}
__device__ __forceinline__ void ldsm4t(uint32_t* r, uint32_t addr) {
    asm volatile("ldmatrix.sync.aligned.m8n8.x4.trans.shared.b16 {%0,%1,%2,%3}, [%4];"
                 : "=r"(r[0]), "=r"(r[1]), "=r"(r[2]), "=r"(r[3]) : "r"(addr));
}
__device__ __forceinline__ void cp16(uint32_t saddr, const void* g) {
    asm volatile("cp.async.ca.shared.global [%0], [%1], 16;" :: "r"(saddr), "l"(g) : "memory");
}
__device__ __forceinline__ void cp_commit() {
    asm volatile("cp.async.commit_group;" ::: "memory");
}
__device__ __forceinline__ void cp_wait0() {
    asm volatile("cp.async.wait_group 0;" ::: "memory");
}
__device__ __forceinline__ void mma_h(float* d, const uint32_t* a, const uint32_t* b) {
    asm volatile("mma.sync.aligned.m16n8k16.row.col.f32.f16.f16.f32 "
                 "{%0,%1,%2,%3}, {%4,%5,%6,%7}, {%8,%9}, {%0,%1,%2,%3};"
                 : "+f"(d[0]), "+f"(d[1]), "+f"(d[2]), "+f"(d[3])
                 : "r"(a[0]), "r"(a[1]), "r"(a[2]), "r"(a[3]), "r"(b[0]), "r"(b[1]));
}
__device__ __forceinline__ float ex2(float x) {
    float r; asm("ex2.approx.f32 %0, %1;" : "=f"(r) : "f"(x)); return r;
}
#define PACKH2(r, lo, hi) \
    asm("cvt.rn.f16x2.f32 %0, %1, %2;" : "=r"(r) : "f"(hi), "f"(lo))

__device__ __forceinline__ float warp_sum(float v) {
    #pragma unroll
    for (int o = 16; o; o >>= 1) v += __shfl_xor_sync(0xffffffffu, v, o);
    return v;
}

// ---------------- prep ----------------
__global__ __launch_bounds__(256)
void qkvpack_k(const float* __restrict__ wq, const float* __restrict__ wk,
               const float* __restrict__ wv, __half* __restrict__ dst)
{
    const int N4 = HIDDEN * HIDDEN / 4;
    int i = blockIdx.x * 256 + threadIdx.x;
    if (i >= 3 * N4) return;
    const float* src = (i < N4) ? wq : (i < 2 * N4) ? wk : wv;
    int j = (i < N4) ? i : (i < 2 * N4) ? i - N4 : i - 2 * N4;
    float4 v = reinterpret_cast<const float4*>(src)[j];
    __half2* d = reinterpret_cast<__half2*>(dst);
    d[2 * i + 0] = __floats2half2_rn(v.x, v.y);
    d[2 * i + 1] = __floats2half2_rn(v.z, v.w);
}

__global__ __launch_bounds__(256)
void halfcpy_k(const float* __restrict__ in, __half* __restrict__ out, int n4)
{
    int i = blockIdx.x * 256 + threadIdx.x;
    if (i < n4) {
        float4 v = reinterpret_cast<const float4*>(in)[i];
        __half2* d = reinterpret_cast<__half2*>(out);
        d[2 * i + 0] = __floats2half2_rn(v.x, v.y);
        d[2 * i + 1] = __floats2half2_rn(v.z, v.w);
    }
}

// ---------------- LayerNorm (fp32 in, fp16 out) ----------------
__global__ __launch_bounds__(256)
void ln_k(const float* __restrict__ x, const float* __restrict__ g,
          const float* __restrict__ b, __half* __restrict__ out)
{
    long row = blockIdx.x;
    const float* xr = x + row * (long)HIDDEN;
    int tid = threadIdx.x;
    float v0 = xr[tid], v1 = xr[tid + 256], v2 = xr[tid + 512];
    float s  = v0 + v1 + v2;
    float s2 = v0 * v0 + v1 * v1 + v2 * v2;
    __shared__ float sh[18];
    s = warp_sum(s); s2 = warp_sum(s2);
    int w = tid >> 5, l = tid & 31;
    if (!l) { sh[w] = s; sh[w + 8] = s2; }
    __syncthreads();
    if (tid == 0) {
        float ts = 0.f, ts2 = 0.f;
        #pragma unroll
        for (int i = 0; i < 8; i++) { ts += sh[i]; ts2 += sh[i + 8]; }
        float mu  = ts * (1.0f / HIDDEN);
        float var = ts2 * (1.0f / HIDDEN) - mu * mu;
        sh[16] = mu; sh[17] = rsqrtf(var + 1e-5f);
    }
    __syncthreads();
    float mu = sh[16], inv = sh[17];
    __half* o = out + row * (long)HIDDEN;
    o[tid]       = __float2half_rn((v0 - mu) * inv * g[tid]       + b[tid]);
    o[tid + 256] = __float2half_rn((v1 - mu) * inv * g[tid + 256] + b[tid + 256]);
    o[tid + 512] = __float2half_rn((v2 - mu) * inv * g[tid + 512] + b[tid + 512]);
}

// ---------------- transpose fp32 -> fp16 (weights) ----------------
__global__ __launch_bounds__(256)
void transpose_k(const float* __restrict__ in, int ldi,
                 __half* __restrict__ out, int ldo)
{
    __shared__ float t[32][33];
    int c0 = blockIdx.x * 32, r0 = blockIdx.y * 32;
    int tx = threadIdx.x & 31, ty = threadIdx.x >> 5;
    #pragma unroll
    for (int i = ty; i < 32; i += 8)
        t[i][tx] = in[(long)(r0 + i) * ldi + c0 + tx];
    __syncthreads();
    #pragma unroll
    for (int i = ty; i < 32; i += 8)
        out[(long)(c0 + i) * ldo + r0 + tx] = __float2half_rn(t[tx][i]);
}

#define FPITCH 144
#define TILEB  (128 * FPITCH)       // 18432
#define LOG2E  1.4426950408889634f

// ---------------- flash attention (fp16, scale pre-folded into Q) ----------------
__global__ __launch_bounds__(256)
void flash_k(const __half* __restrict__ Qb, const __half* __restrict__ Kb,
             const __half* __restrict__ Vg, __half* __restrict__ Og)
{
    extern __shared__ char sm[];
    uint32_t qsb = smem_u32(sm);
    uint32_t ksb = qsb + TILEB;
    uint32_t vsb = qsb + 3 * TILEB;

    int tid = threadIdx.x, lane = tid & 31, wid = tid >> 5;
    int qr = lane >> 2, qc = lane & 3;
    int z = blockIdx.y;
    int b = z / HEADS, h = z - b * HEADS;
    int q0 = blockIdx.x * 128;
    long tokbase = (long)b * SEQ + q0;

    const __half* Qp = Qb + tokbase * HIDDEN + h * HEAD_DIM;
    const __half* Kp = Kb + (long)b * SEQ * HIDDEN + h * HEAD_DIM;
    const __half* Vp = Vg + (long)b * SEQ * HIDDEN + h * HEAD_DIM;

    #pragma unroll
    for (int i = 0; i < 4; i++) {
        int f = tid + i * 256; int r = f >> 3, u = f & 7;
        cp16(qsb + r * FPITCH + u * 16, Qp + (long)r * HIDDEN + u * 8);
        cp16(ksb + r * FPITCH + u * 16, Kp + (long)r * HIDDEN + u * 8);
        cp16(vsb + r * FPITCH + u * 16, Vp + (long)r * HIDDEN + u * 8);
    }
    cp_commit();
    cp_wait0();
    __syncthreads();

    int rQ = wid * 16 + ((lane >> 3) & 1) * 8 + (lane & 7);
    int hiQ = lane >> 4;
    uint32_t qf[4][4];
    #pragma unroll
    for (int ks = 0; ks < 4; ks++)
        ldsm4(qf[ks], qsb + rQ * FPITCH + ks * 32 + hiQ * 16);

    int rK = ((lane >> 4) & 1) * 8 + (lane & 7);
    int hiK = (lane >> 3) & 1;
    int rV = ((lane >> 3) & 1) * 8 + (lane & 7);
    int hiV = lane >> 4;

    float oa[8][4];
    #pragma unroll
    for (int i = 0; i < 8; i++)
        #pragma unroll
        for (int e = 0; e < 4; e++) oa[i][e] = 0.f;
    float mA = -1e30f, mB = -1e30f, lA = 0.f, lB = 0.f;

    for (int ch = 0; ch < SEQ / 128; ch++) {
        int buf = ch & 1;
        uint32_t kbuf = ksb + buf * TILEB;
        uint32_t vbuf = vsb + buf * TILEB;

        // S = Q @ K^T (Q pre-scaled by 1/8)
        float sa[16][4];
        #pragma unroll
        for (int i = 0; i < 16; i++)
            #pragma unroll
            for (int e = 0; e < 4; e++) sa[i][e] = 0.f;
        #pragma unroll
        for (int ks = 0; ks < 4; ks++) {
            #pragma unroll
            for (int ntp = 0; ntp < 8; ntp++) {
                uint32_t bf[4];
                ldsm4(bf, kbuf + (rK + ntp * 16) * FPITCH + ks * 32 + hiK * 16);
                mma_h(sa[2 * ntp + 0], qf[ks], bf);
                mma_h(sa[2 * ntp + 1], qf[ks], bf + 2);
            }
        }

        if (ch + 1 < SEQ / 128) {
            const __half* Kn = Kp + (long)(ch + 1) * 128 * HIDDEN;
            const __half* Vn = Vp + (long)(ch + 1) * 128 * HIDDEN;
            uint32_t kdst = ksb + (buf ^ 1) * TILEB;
            uint32_t vdst = vsb + (buf ^ 1) * TILEB;
            #pragma unroll
            for (int i = 0; i < 4; i++) {
                int f = tid + i * 256; int r = f >> 3, u = f & 7;
                cp16(kdst + r * FPITCH + u * 16, Kn + (long)r * HIDDEN + u * 8);
                cp16(vdst + r * FPITCH + u * 16, Vn + (long)r * HIDDEN + u * 8);
            }
            cp_commit();
        }

        // online softmax via ex2 (1 FMA + 1 EX2 per element)
        float rmA = -1e30f, rmB = -1e30f;
        #pragma unroll
        for (int nt = 0; nt < 16; nt++) {
            rmA = fmaxf(rmA, fmaxf(sa[nt][0], sa[nt][1]));
            rmB = fmaxf(rmB, fmaxf(sa[nt][2], sa[nt][3]));
        }
        rmA = fmaxf(rmA, __shfl_xor_sync(0xffffffffu, rmA, 1));
        rmA = fmaxf(rmA, __shfl_xor_sync(0xffffffffu, rmA, 2));
        rmB = fmaxf(rmB, __shfl_xor_sync(0xffffffffu, rmB, 1));
        rmB = fmaxf(rmB, __shfl_xor_sync(0xffffffffu, rmB, 2));
        float mAn = fmaxf(mA, rmA), mBn = fmaxf(mB, rmB);
        float aA = ex2((mA - mAn) * LOG2E), aB = ex2((mB - mBn) * LOG2E);
        float mcA = mAn * LOG2E, mcB = mBn * LOG2E;
        float sA = 0.f, sB = 0.f;
        #pragma unroll
        for (int nt = 0; nt < 16; nt++) {
            sa[nt][0] = ex2(__fmaf_rn(sa[nt][0], LOG2E, -mcA));
            sa[nt][1] = ex2(__fmaf_rn(sa[nt][1], LOG2E, -mcA));
            sa[nt][2] = ex2(__fmaf_rn(sa[nt][2], LOG2E, -mcB));
            sa[nt][3] = ex2(__fmaf_rn(sa[nt][3], LOG2E, -mcB));
            sA += sa[nt][0] + sa[nt][1];
            sB += sa[nt][2] + sa[nt][3];
        }
        sA += __shfl_xor_sync(0xffffffffu, sA, 1);
        sA += __shfl_xor_sync(0xffffffffu, sA, 2);
        sB += __shfl_xor_sync(0xffffffffu, sB, 1);
        sB += __shfl_xor_sync(0xffffffffu, sB, 2);
        lA = aA * lA + sA;  lB = aB * lB + sB;
        mA = mAn;  mB = mBn;
        #pragma unroll
        for (int nt = 0; nt < 8; nt++) {
            oa[nt][0] *= aA; oa[nt][1] *= aA;
            oa[nt][2] *= aB; oa[nt][3] *= aB;
        }

        // O += P @ V (P pairs are fp16 A-frags; V via ldmatrix.trans)
        #pragma unroll
        for (int j = 0; j < 8; j++) {
            uint32_t af[4];
            PACKH2(af[0], sa[2 * j][0],     sa[2 * j][1]);
            PACKH2(af[1], sa[2 * j][2],     sa[2 * j][3]);
            PACKH2(af[2], sa[2 * j + 1][0], sa[2 * j + 1][1]);
            PACKH2(af[3], sa[2 * j + 1][2], sa[2 * j + 1][3]);
            #pragma unroll
            for (int dp = 0; dp < 4; dp++) {
                uint32_t bf[4];
                ldsm4t(bf, vbuf + (16 * j + rV) * FPITCH + dp * 32 + hiV * 16);
                mma_h(oa[2 * dp + 0], af, bf);
                mma_h(oa[2 * dp + 1], af, bf + 2);
            }
        }

        cp_wait0();
        __syncthreads();
    }

    float rA = 1.f / lA, rB = 1.f / lB;
    long rowA = tokbase + wid * 16 + qr;
    __half* OA = Og + rowA * HIDDEN + h * HEAD_DIM;
    __half* OB = OA + 8 * HIDDEN;
    #pragma unroll
    for (int nt = 0; nt < 8; nt++) {
        int col = nt * 8 + 2 * qc;
        *reinterpret_cast<__half2*>(OA + col) = __floats2half2_rn(oa[nt][0] * rA, oa[nt][1] * rA);
        *reinterpret_cast<__half2*>(OB + col) = __floats2half2_rn(oa[nt][2] * rB, oa[nt][3] * rB);
    }
}

// ---------------- fp16 GEMM, 128x128, BK=64, 2 CTAs/SM ----------------
// EPI: 1 -> fp32 +bias+resid out; 2 -> fp16 +bias+GELU out.
template<int EPI>
__global__ __launch_bounds__(256, 2)
void gemm_h(const __half* __restrict__ A, int lda,
            const __half* __restrict__ B, int ldb,
            void* __restrict__ Cv, int ldc, int K,
            const float* __restrict__ bias,
            const float* __restrict__ resid, int ldr)
{
    constexpr int MT = 4, NT = 4;
    constexpr int ABUF = 2 * TILEB;
    extern __shared__ char sm[];
    uint32_t sbase = smem_u32(sm);

    int tid = threadIdx.x, lane = tid & 31, wid = tid >> 5;
    int wr = wid >> 2, wc = wid & 3;
    int m0 = blockIdx.y * 128, n0 = blockIdx.x * 128;

    const __half* Ag = A + (long)m0 * lda;
    const __half* Bg = B + (long)n0 * ldb;

    int rA = wr * 64 + ((lane >> 3) & 1) * 8 + (lane & 7);
    int hiA = lane >> 4;
    int rB = wc * 32 + ((lane >> 4) & 1) * 8 + (lane & 7);
    int hiB = (lane >> 3) & 1;

    float acc[MT][NT][4];
    #pragma unroll
    for (int i = 0; i < MT; i++)
        #pragma unroll
        for (int j = 0; j < NT; j++)
            #pragma unroll
            for (int e = 0; e < 4; e++) acc[i][j][e] = 0.f;

    int nCh = K >> 6;

    #pragma unroll
    for (int i = 0; i < 4; i++) {
        int f = tid + i * 256; int r = f >> 3, u = f & 7;
        cp16(sbase + r * FPITCH + u * 16, Ag + (long)r * lda + u * 8);
        cp16(sbase + TILEB + r * FPITCH + u * 16, Bg + (long)r * ldb + u * 8);
    }
    cp_commit();

    for (int c = 0; c < nCh; ++c) {
        int buf = c & 1;
        cp_wait0();
        __syncthreads();
        if (c + 1 < nCh) {
            const __half* An = Ag + (c + 1) * 64;
            const __half* Bn = Bg + (c + 1) * 64;
            uint32_t dst = sbase + (buf ^ 1) * ABUF;
            #pragma unroll
            for (int i = 0; i < 4; i++) {
                int f = tid + i * 256; int r = f >> 3, u = f & 7;
                cp16(dst + r * FPITCH + u * 16, An + (long)r * lda + u * 8);
                cp16(dst + TILEB + r * FPITCH + u * 16, Bn + (long)r * ldb + u * 8);
            }
            cp_commit();
        }

        uint32_t aB = sbase + buf * ABUF;
        uint32_t bB = aB + TILEB;

        #pragma unroll
        for (int ks = 0; ks < 4; ++ks) {
            uint32_t af[MT][4], bf[NT / 2][4];
            #pragma unroll
            for (int mt = 0; mt < MT; mt++)
                ldsm4(af[mt], aB + (rA + mt * 16) * FPITCH + ks * 32 + hiA * 16);
            #pragma unroll
            for (int ntp = 0; ntp < NT / 2; ntp++)
                ldsm4(bf[ntp], bB + (rB + ntp * 16) * FPITCH + ks * 32 + hiB * 16);
            #pragma unroll
            for (int mt = 0; mt < MT; mt++)
                #pragma unroll
                for (int ntp = 0; ntp < NT / 2; ntp++) {
                    mma_h(acc[mt][2 * ntp + 0], af[mt], bf[ntp]);
                    mma_h(acc[mt][2 * ntp + 1], af[mt], bf[ntp] + 2);
                }
        }
        __syncthreads();
    }

    int qr = lane >> 2, qc = lane & 3;
    #pragma unroll
    for (int mt = 0; mt < MT; mt++) {
        #pragma unroll
        for (int half = 0; half < 2; half++) {
            int row = m0 + wr * 64 + mt * 16 + qr + half * 8;
            const float* Rrow = (EPI == 1) ? (resid + (long)row * ldr) : nullptr;
            #pragma unroll
            for (int nt = 0; nt < NT; nt++) {
                int col = n0 + wc * 32 + nt * 8 + 2 * qc;
                float v0 = acc[mt][nt][half * 2 + 0];
                float v1 = acc[mt][nt][half * 2 + 1];
                if (EPI == 1) {
                    v0 += bias[col]     + Rrow[col];
                    v1 += bias[col + 1] + Rrow[col + 1];
                    float* Crow = (float*)Cv + (long)row * ldc;
                    *reinterpret_cast<float2*>(&Crow[col]) = make_float2(v0, v1);
                } else {
                    v0 += bias[col];
                    v1 += bias[col + 1];
                    v0 = 0.5f * v0 * (1.0f + erff(v0 * 0.70710678118654752f));
                    v1 = 0.5f * v1 * (1.0f + erff(v1 * 0.70710678118654752f));
                    __half* Crow = (__half*)Cv + (long)row * ldc;
                    *reinterpret_cast<__half2*>(&Crow[col]) = __floats2half2_rn(v0, v1);
                }
            }
        }
    }
}

// ---------------- QKV GEMM: 3D grid, z selects weight/output; Q scaled 1/8 ----------------
__global__ __launch_bounds__(256, 2)
void gemm_qkv(const __half* __restrict__ A, int lda,
              const __half* __restrict__ Bw, __half* __restrict__ Cb, int K)
{
    constexpr int MT = 4, NT = 4;
    constexpr int ABUF = 2 * TILEB;
    extern __shared__ char sm[];
    uint32_t sbase = smem_u32(sm);

    int tid = threadIdx.x, lane = tid & 31, wid = tid >> 5;
    int wr = wid >> 2, wc = wid & 3;
    int zz = blockIdx.z;
    int m0 = blockIdx.y * 128, n0 = blockIdx.x * 128;
    float osc = (zz == 0) ? 0.125f : 1.0f;

    const __half* Ag = A + (long)m0 * lda;
    const __half* Bg = Bw + (long)zz * HIDDEN * HIDDEN + (long)n0 * HIDDEN;
    __half* C = Cb + (long)zz * MTOK * HIDDEN;

    int rA = wr * 64 + ((lane >> 3) & 1) * 8 + (lane & 7);
    int hiA = lane >> 4;
    int rB = wc * 32 + ((lane >> 4) & 1) * 8 + (lane & 7);
    int hiB = (lane >> 3) & 1;

    float acc[MT][NT][4];
    #pragma unroll
    for (int i = 0; i < MT; i++)
        #pragma unroll
        for (int j = 0; j < NT; j++)
            #pragma unroll
            for (int e = 0; e < 4; e++) acc[i][j][e] = 0.f;

    int nCh = K >> 6;

    #pragma unroll
    for (int i = 0; i < 4; i++) {
        int f = tid + i * 256; int r = f >> 3, u = f & 7;
        cp16(sbase + r * FPITCH + u * 16, Ag + (long)r * lda + u * 8);
        cp16(sbase + TILEB + r * FPITCH + u * 16, Bg + (long)r * HIDDEN + u * 8);
    }
    cp_commit();

    for (int c = 0; c < nCh; ++c) {
        int buf = c & 1;
        cp_wait0();
        __syncthreads();
        if (c + 1 < nCh) {
            const __half* An = Ag + (c + 1) * 64;
            const __half* Bn = Bg + (c + 1) * 64;
            uint32_t dst = sbase + (buf ^ 1) * ABUF;
            #pragma unroll
            for (int i = 0; i < 4; i++) {
                int f = tid + i * 256; int r = f >> 3, u = f & 7;
                cp16(dst + r * FPITCH + u * 16, An + (long)r * lda + u * 8);
                cp16(dst + TILEB + r * FPITCH + u * 16, Bn + (long)r * HIDDEN + u * 8);
            }
            cp_commit();
        }

        uint32_t aB = sbase + buf * ABUF;
        uint32_t bB = aB + TILEB;

        #pragma unroll
        for (int ks = 0; ks < 4; ++ks) {
            uint32_t af[MT][4], bf[NT / 2][4];
            #pragma unroll
            for (int mt = 0; mt < MT; mt++)
                ldsm4(af[mt], aB + (rA + mt * 16) * FPITCH + ks * 32 + hiA * 16);
            #pragma unroll
            for (int ntp = 0; ntp < NT / 2; ntp++)
                ldsm4(bf[ntp], bB + (rB + ntp * 16) * FPITCH + ks * 32 + hiB * 16);
            #pragma unroll
            for (int mt = 0; mt < MT; mt++)
                #pragma unroll
                for (int ntp = 0; ntp < NT / 2; ntp++) {
                    mma_h(acc[mt][2 * ntp + 0], af[mt], bf[ntp]);
                    mma_h(acc[mt][2 * ntp + 1], af[mt], bf[ntp] + 2);
                }
        }
        __syncthreads();
    }

    int qr = lane >> 2, qc = lane & 3;
    #pragma unroll
    for (int mt = 0; mt < MT; mt++) {
        #pragma unroll
        for (int half = 0; half < 2; half++) {
            int row = m0 + wr * 64 + mt * 16 + qr + half * 8;
            __half* Crow = C + (long)row * HIDDEN;
            #pragma unroll
            for (int nt = 0; nt < NT; nt++) {
                int col = n0 + wc * 32 + nt * 8 + 2 * qc;
                float v0 = acc[mt][nt][half * 2 + 0] * osc;
                float v1 = acc[mt][nt][half * 2 + 1] * osc;
                *reinterpret_cast<__half2*>(&Crow[col]) = __floats2half2_rn(v0, v1);
            }
        }
    }
}

// ---------------- fp16 GEMM, 128x256, BK=64, 1 CTA/SM (MLP) ----------------
#define BTILEB (256 * FPITCH)     // 36864
template<int EPI>
__global__ __launch_bounds__(256, 1)
void gemm_w(const __half* __restrict__ A, int lda,
            const __half* __restrict__ B, int ldb,
            void* __restrict__ Cv, int ldc, int K,
            const float* __restrict__ bias,
            const float* __restrict__ resid, int ldr)
{
    constexpr int MT = 4, NT = 8;
    constexpr int ABUF = TILEB + BTILEB;   // per-buffer stride
    extern __shared__ char sm[];
    uint32_t sbase = smem_u32(sm);

    int tid = threadIdx.x, lane = tid & 31, wid = tid >> 5;
    int wr = wid >> 2, wc = wid & 3;
    int m0 = blockIdx.y * 128, n0 = blockIdx.x * 256;

    const __half* Ag = A + (long)m0 * lda;
    const __half* Bg = B + (long)n0 * ldb;

    int rA = wr * 64 + ((lane >> 3) & 1) * 8 + (lane & 7);
    int hiA = lane >> 4;
    int rB = wc * 64 + ((lane >> 4) & 1) * 8 + (lane & 7);
    int hiB = (lane >> 3) & 1;

    float acc[MT][NT][4];
    #pragma unroll
    for (int i = 0; i < MT; i++)
        #pragma unroll
        for (int j = 0; j < NT; j++)
            #pragma unroll
            for (int e = 0; e < 4; e++) acc[i][j][e] = 0.f;

    int nCh = K >> 6;

    // stage: A 1024 units + B 2048 units = 3072, 12 per thread
    #pragma unroll
    for (int i = 0; i < 4; i++) {
        int f = tid + i * 256; int r = f >> 3, u = f & 7;
        cp16(sbase + r * FPITCH + u * 16, Ag + (long)r * lda + u * 8);
    }
    #pragma unroll
    for (int i = 0; i < 8; i++) {
        int f = tid + i * 256; int r = f >> 3, u = f & 7;
        cp16(sbase + TILEB + r * FPITCH + u * 16, Bg + (long)r * ldb + u * 8);
    }
    cp_commit();

    for (int c = 0; c < nCh; ++c) {
        int buf = c & 1;
        cp_wait0();
        __syncthreads();
        if (c + 1 < nCh) {
            const __half* An = Ag + (c + 1) * 64;
            const __half* Bn = Bg + (c + 1) * 64;
            uint32_t dst = sbase + (buf ^ 1) * ABUF;
            #pragma unroll
            for (int i = 0; i < 4; i++) {
                int f = tid + i * 256; int r = f >> 3, u = f & 7;
                cp16(dst + r * FPITCH + u * 16, An + (long)r * lda + u * 8);
            }
            #pragma unroll
            for (int i = 0; i < 8; i++) {
                int f = tid + i * 256; int r = f >> 3, u = f & 7;
                cp16(dst + TILEB + r * FPITCH + u * 16, Bn + (long)r * ldb + u * 8);
            }
            cp_commit();
        }

        uint32_t aB = sbase + buf * ABUF;
        uint32_t bB = aB + TILEB;

        #pragma unroll
        for (int ks = 0; ks < 4; ++ks) {
            uint32_t af[MT][4], bf[NT / 2][4];
            #pragma unroll
            for (int mt = 0; mt < MT; mt++)
                ldsm4(af[mt], aB + (rA + mt * 16) * FPITCH + ks * 32 + hiA * 16);
            #pragma unroll
            for (int ntp = 0; ntp < NT / 2; ntp++)
                ldsm4(bf[ntp], bB + (rB + ntp * 16) * FPITCH + ks * 32 + hiB * 16);
            #pragma unroll
            for (int mt = 0; mt < MT; mt++)
                #pragma unroll
                for (int ntp = 0; ntp < NT / 2; ntp++) {
                    mma_h(acc[mt][2 * ntp + 0], af[mt], bf[ntp]);
                    mma_h(acc[mt][2 * ntp + 1], af[mt], bf[ntp] + 2);
                }
        }
        __syncthreads();
    }

    int qr = lane >> 2, qc = lane & 3;
    #pragma unroll
    for (int mt = 0; mt < MT; mt++) {
        #pragma unroll
        for (int half = 0; half < 2; half++) {
            int row = m0 + wr * 64 + mt * 16 + qr + half * 8;
            const float* Rrow = (EPI == 1) ? (resid + (long)row * ldr) : nullptr;
            #pragma unroll
            for (int nt = 0; nt < NT; nt++) {
                int col = n0 + wc * 64 + nt * 8 + 2 * qc;
                float v0 = acc[mt][nt][half * 2 + 0];
                float v1 = acc[mt][nt][half * 2 + 1];
                if (EPI == 1) {
                    v0 += bias[col]     + Rrow[col];
                    v1 += bias[col + 1] + Rrow[col + 1];
                    float* Crow = (float*)Cv + (long)row * ldc;
                    *reinterpret_cast<float2*>(&Crow[col]) = make_float2(v0, v1);
                } else {
                    v0 += bias[col];
                    v1 += bias[col + 1];
                    v0 = 0.5f * v0 * (1.0f + erff(v0 * 0.70710678118654752f));
                    v1 = 0.5f * v1 * (1.0f + erff(v1 * 0.70710678118654752f));
                    __half* Crow = (__half*)Cv + (long)row * ldc;
                    *reinterpret_cast<__half2*>(&Crow[col]) = __floats2half2_rn(v0, v1);
                }
            }
        }
    }
}

// ---------------- launcher ----------------
extern "C" void kernel_launch(void* const* d_in, const int* in_sizes, int n_in,
                              void* d_out, int out_size)
{
    const float* x    = (const float*)d_in[0];
    const float* ln1g = (const float*)d_in[1];
    const float* ln1b = (const float*)d_in[2];
    const float* wq   = (const float*)d_in[3];
    const float* wk   = (const float*)d_in[4];
    const float* wv   = (const float*)d_in[5];
    const float* wo   = (const float*)d_in[6];
    const float* bo   = (const float*)d_in[7];
    const float* ln2g = (const float*)d_in[8];
    const float* ln2b = (const float*)d_in[9];
    const float* w1   = (const float*)d_in[10];
    const float* b1   = (const float*)d_in[11];
    const float* w2   = (const float*)d_in[12];
    const float* b2   = (const float*)d_in[13];
    float* out = (float*)d_out;

    __half *xn, *qkv, *attn, *hm, *w1t, *w2t, *rwqkv, *rwo;
    float* x1;
    cudaGetSymbolAddress((void**)&xn,    g_xn);
    cudaGetSymbolAddress((void**)&qkv,   g_qkv);
    cudaGetSymbolAddress((void**)&attn,  g_attn);
    cudaGetSymbolAddress((void**)&x1,    g_x1);
    cudaGetSymbolAddress((void**)&hm,    g_h);
    cudaGetSymbolAddress((void**)&w1t,   g_w1t);
    cudaGetSymbolAddress((void**)&w2t,   g_w2t);
    cudaGetSymbolAddress((void**)&rwqkv, g_wqkv);
    cudaGetSymbolAddress((void**)&rwo,   g_wo);

    __half* qb = qkv;
    __half* kb = qkv + (size_t)MTOK * HIDDEN;
    __half* vb = qkv + (size_t)2 * MTOK * HIDDEN;

    const int SMGE = 4 * TILEB;                 // 73728
    const int SMGW = 2 * (TILEB + BTILEB);      // 110592
    const int SMFL = 5 * TILEB;                 // 92160
    cudaFuncSetAttribute((const void*)gemm_h<1>, cudaFuncAttributeMaxDynamicSharedMemorySize, SMGE);
    cudaFuncSetAttribute((const void*)gemm_qkv,  cudaFuncAttributeMaxDynamicSharedMemorySize, SMGE);
    cudaFuncSetAttribute((const void*)gemm_w<1>, cudaFuncAttributeMaxDynamicSharedMemorySize, SMGW);
    cudaFuncSetAttribute((const void*)gemm_w<2>, cudaFuncAttributeMaxDynamicSharedMemorySize, SMGW);
    cudaFuncSetAttribute((const void*)flash_k,   cudaFuncAttributeMaxDynamicSharedMemorySize, SMFL);

    // prep
    int nw = HIDDEN * HIDDEN / 4;
    qkvpack_k<<<(3 * nw + 255) / 256, 256>>>(wq, wk, wv, rwqkv);
    halfcpy_k<<<(nw + 255) / 256, 256>>>(wo, rwo, nw);
    transpose_k<<<dim3(MLPH / 32, HIDDEN / 32), 256>>>(w1, MLPH, w1t, HIDDEN);
    transpose_k<<<dim3(HIDDEN / 32, MLPH / 32), 256>>>(w2, HIDDEN, w2t, MLPH);

    // 1. LN1
    ln_k<<<MTOK, 256>>>(x, ln1g, ln1b, xn);

    // 2. QKV: one 3D launch (Q pre-scaled by 1/8)
    gemm_qkv<<<dim3(HIDDEN / 128, MTOK / 128, 3), 256, SMGE>>>(xn, HIDDEN, rwqkv, qkv, HIDDEN);

    // 3. fused attention
    flash_k<<<dim3(SEQ / 128, BATCH * HEADS), 256, SMFL>>>(qb, kb, vb, attn);

    // 4. x1 = attn @ wo^T + bo + x
    dim3 gH(HIDDEN / 128, MTOK / 128);
    gemm_h<1><<<gH, 256, SMGE>>>(attn, HIDDEN, rwo, HIDDEN, x1, HIDDEN, HIDDEN, bo, x, HIDDEN);

    // 5. LN2
    ln_k<<<MTOK, 256>>>(x1, ln2g, ln2b, xn);

    // 6. h = gelu(xn @ w1 + b1)  (128x256 tile)
    gemm_w<2><<<dim3(MLPH / 256, MTOK / 128), 256, SMGW>>>(
        xn, HIDDEN, w1t, HIDDEN, hm, MLPH, HIDDEN, b1, nullptr, 0);

    // 7. out = h @ w2 + b2 + x1  (128x256 tile)
    gemm_w<1><<<dim3(HIDDEN / 256, MTOK / 128), 256, SMGW>>>(
        hm, MLPH, w2t, MLPH, out, HIDDEN, MLPH, b2, x1, HIDDEN);
}

// round 13
// speedup vs baseline: 1.0302x; 1.0302x over previous
#include <cuda_runtime.h>
#include <cuda_fp16.h>
#include <math.h>
#include <stdint.h>

// ---------------- problem constants ----------------
#define HIDDEN   768
#define MLPH     3072
#define HEADS    12
#define HEAD_DIM 64
#define BATCH    16
#define SEQ      1024
#define MTOK     (BATCH * SEQ)

// ---------------- scratch ----------------
__device__ __align__(16) __half g_xn  [(size_t)MTOK * HIDDEN];
__device__ __align__(16) __half g_qkv [(size_t)3 * MTOK * HIDDEN];
__device__ __align__(16) __half g_attn[(size_t)MTOK * HIDDEN];
__device__ __align__(16) float  g_x1  [(size_t)MTOK * HIDDEN];
__device__ __align__(16) __half g_h   [(size_t)MTOK * MLPH];
__device__ __align__(16) __half g_w1t [(size_t)MLPH * HIDDEN];
__device__ __align__(16) __half g_w2t [(size_t)HIDDEN * MLPH];
__device__ __align__(16) __half g_wqkv[(size_t)3 * HIDDEN * HIDDEN];
__device__ __align__(16) __half g_wo  [(size_t)HIDDEN * HIDDEN];

// ---------------- helpers ----------------
__device__ __forceinline__ uint32_t smem_u32(const void* p) {
    uint32_t a;
    asm("{ .reg .u64 t; cvta.to.shared.u64 t, %1; cvt.u32.u64 %0, t; }" : "=r"(a) : "l"(p));
    return a;
}
__device__ __forceinline__ void ldsm4(uint32_t* r, uint32_t addr) {
    asm volatile("ldmatrix.sync.aligned.m8n8.x4.shared.b16 {%0,%1,%2,%3}, [%4];"
                 : "=r"(r[0]), "=r"(r[1]), "=r"(r[2]), "=r"(r[3]) : "r"(addr));
}
__device__ __forceinline__ void ldsm4t(uint32_t* r, uint32_t addr) {
    asm volatile("ldmatrix.sync.aligned.m8n8.x4.trans.shared.b16 {%0,%1,%2,%3}, [%4];"
                 : "=r"(r[0]), "=r"(r[1]), "=r"(r[2]), "=r"(r[3]) : "r"(addr));
}
__device__ __forceinline__ void cp16(uint32_t saddr, const void* g) {
    asm volatile("cp.async.ca.shared.global [%0], [%1], 16;" :: "r"(saddr), "l"(g) : "memory");
}
__device__ __forceinline__ void cp_commit() {
    asm volatile("cp.async.commit_group;" ::: "memory");
}
__device__ __forceinline__ void cp_wait0() {
    asm volatile("cp.async.wait_group 0;" ::: "memory");
}
__device__ __forceinline__ void mma_h(float* d, const uint32_t* a, const uint32_t* b) {
    asm volatile("mma.sync.aligned.m16n8k16.row.col.f32.f16.f16.f32 "
                 "{%0,%1,%2,%3}, {%4,%5,%6,%7}, {%8,%9}, {%0,%1,%2,%3};"
                 : "+f"(d[0]), "+f"(d[1]), "+f"(d[2]), "+f"(d[3])
                 : "r"(a[0]), "r"(a[1]), "r"(a[2]), "r"(a[3]), "r"(b[0]), "r"(b[1]));
}
__device__ __forceinline__ float ex2(float x) {
    float r; asm("ex2.approx.f32 %0, %1;" : "=f"(r) : "f"(x)); return r;
}
// pack two fp32 -> fp16x2 (.x = lo, .y = hi)
#define PACKH2(r, lo, hi) \
    asm("cvt.rn.f16x2.f32 %0, %1, %2;" : "=r"(r) : "f"(hi), "f"(lo))
__device__ __forceinline__ uint32_t ex2h2(uint32_t a) {
    uint32_t r; asm("ex2.approx.f16x2 %0, %1;" : "=r"(r) : "r"(a)); return r;
}
__device__ __forceinline__ float warp_sum(float v) {
    #pragma unroll
    for (int o = 16; o; o >>= 1) v += __shfl_xor_sync(0xffffffffu, v, o);
    return v;
}

// ---------------- prep: round/pack all 4 hidden-square weights ----------------
// z-major index: i in [0, 4*N4): 0..N4 wq, .. wk, .. wv, .. wo
__global__ __launch_bounds__(256)
void wpack_k(const float* __restrict__ wq, const float* __restrict__ wk,
             const float* __restrict__ wv, const float* __restrict__ wo,
             __half* __restrict__ dqkv, __half* __restrict__ dwo)
{
    const int N4 = HIDDEN * HIDDEN / 4;
    int i = blockIdx.x * 256 + threadIdx.x;
    if (i >= 4 * N4) return;
    int seg = i / N4, j = i - seg * N4;
    const float* src = (seg == 0) ? wq : (seg == 1) ? wk : (seg == 2) ? wv : wo;
    __half* dst = (seg == 3) ? dwo : dqkv + (size_t)seg * HIDDEN * HIDDEN;
    float4 v = reinterpret_cast<const float4*>(src)[j];
    __half2* d = reinterpret_cast<__half2*>(dst);
    d[2 * j + 0] = __floats2half2_rn(v.x, v.y);
    d[2 * j + 1] = __floats2half2_rn(v.z, v.w);
}

// ---------------- LayerNorm (fp32 in, fp16 out) ----------------
__global__ __launch_bounds__(256)
void ln_k(const float* __restrict__ x, const float* __restrict__ g,
          const float* __restrict__ b, __half* __restrict__ out)
{
    long row = blockIdx.x;
    const float* xr = x + row * (long)HIDDEN;
    int tid = threadIdx.x;
    float v0 = xr[tid], v1 = xr[tid + 256], v2 = xr[tid + 512];
    float s  = v0 + v1 + v2;
    float s2 = v0 * v0 + v1 * v1 + v2 * v2;
    __shared__ float sh[18];
    s = warp_sum(s); s2 = warp_sum(s2);
    int w = tid >> 5, l = tid & 31;
    if (!l) { sh[w] = s; sh[w + 8] = s2; }
    __syncthreads();
    if (tid == 0) {
        float ts = 0.f, ts2 = 0.f;
        #pragma unroll
        for (int i = 0; i < 8; i++) { ts += sh[i]; ts2 += sh[i + 8]; }
        float mu  = ts * (1.0f / HIDDEN);
        float var = ts2 * (1.0f / HIDDEN) - mu * mu;
        sh[16] = mu; sh[17] = rsqrtf(var + 1e-5f);
    }
    __syncthreads();
    float mu = sh[16], inv = sh[17];
    __half* o = out + row * (long)HIDDEN;
    o[tid]       = __float2half_rn((v0 - mu) * inv * g[tid]       + b[tid]);
    o[tid + 256] = __float2half_rn((v1 - mu) * inv * g[tid + 256] + b[tid + 256]);
    o[tid + 512] = __float2half_rn((v2 - mu) * inv * g[tid + 512] + b[tid + 512]);
}

// ---------------- transpose fp32 -> fp16 (weights) ----------------
__global__ __launch_bounds__(256)
void transpose_k(const float* __restrict__ in, int ldi,
                 __half* __restrict__ out, int ldo)
{
    __shared__ float t[32][33];
    int c0 = blockIdx.x * 32, r0 = blockIdx.y * 32;
    int tx = threadIdx.x & 31, ty = threadIdx.x >> 5;
    #pragma unroll
    for (int i = ty; i < 32; i += 8)
        t[i][tx] = in[(long)(r0 + i) * ldi + c0 + tx];
    __syncthreads();
    #pragma unroll
    for (int i = ty; i < 32; i += 8)
        out[(long)(c0 + i) * ldo + r0 + tx] = __float2half_rn(t[tx][i]);
}

#define FPITCH 144
#define TILEB  (128 * FPITCH)       // 18432
#define LOG2E  1.4426950408889634f

// ---------------- flash attention (fp16; scale folded into Q; fp16x2 exp) ----------------
__global__ __launch_bounds__(256)
void flash_k(const __half* __restrict__ Qb, const __half* __restrict__ Kb,
             const __half* __restrict__ Vg, __half* __restrict__ Og)
{
    extern __shared__ char sm[];
    uint32_t qsb = smem_u32(sm);
    uint32_t ksb = qsb + TILEB;
    uint32_t vsb = qsb + 3 * TILEB;

    int tid = threadIdx.x, lane = tid & 31, wid = tid >> 5;
    int qr = lane >> 2, qc = lane & 3;
    int z = blockIdx.y;
    int b = z / HEADS, h = z - b * HEADS;
    int q0 = blockIdx.x * 128;
    long tokbase = (long)b * SEQ + q0;

    const __half* Qp = Qb + tokbase * HIDDEN + h * HEAD_DIM;
    const __half* Kp = Kb + (long)b * SEQ * HIDDEN + h * HEAD_DIM;
    const __half* Vp = Vg + (long)b * SEQ * HIDDEN + h * HEAD_DIM;

    #pragma unroll
    for (int i = 0; i < 4; i++) {
        int f = tid + i * 256; int r = f >> 3, u = f & 7;
        cp16(qsb + r * FPITCH + u * 16, Qp + (long)r * HIDDEN + u * 8);
        cp16(ksb + r * FPITCH + u * 16, Kp + (long)r * HIDDEN + u * 8);
        cp16(vsb + r * FPITCH + u * 16, Vp + (long)r * HIDDEN + u * 8);
    }
    cp_commit();
    cp_wait0();
    __syncthreads();

    int rQ = wid * 16 + ((lane >> 3) & 1) * 8 + (lane & 7);
    int hiQ = lane >> 4;
    uint32_t qf[4][4];
    #pragma unroll
    for (int ks = 0; ks < 4; ks++)
        ldsm4(qf[ks], qsb + rQ * FPITCH + ks * 32 + hiQ * 16);

    int rK = ((lane >> 4) & 1) * 8 + (lane & 7);
    int hiK = (lane >> 3) & 1;
    int rV = ((lane >> 3) & 1) * 8 + (lane & 7);
    int hiV = lane >> 4;

    float oa[8][4];
    #pragma unroll
    for (int i = 0; i < 8; i++)
        #pragma unroll
        for (int e = 0; e < 4; e++) oa[i][e] = 0.f;
    float mA = -1e30f, mB = -1e30f, lA = 0.f, lB = 0.f;

    for (int ch = 0; ch < SEQ / 128; ch++) {
        int buf = ch & 1;
        uint32_t kbuf = ksb + buf * TILEB;
        uint32_t vbuf = vsb + buf * TILEB;

        // S = Q @ K^T (Q pre-scaled by 1/8)
        float sa[16][4];
        #pragma unroll
        for (int i = 0; i < 16; i++)
            #pragma unroll
            for (int e = 0; e < 4; e++) sa[i][e] = 0.f;
        #pragma unroll
        for (int ks = 0; ks < 4; ks++) {
            #pragma unroll
            for (int ntp = 0; ntp < 8; ntp++) {
                uint32_t bf[4];
                ldsm4(bf, kbuf + (rK + ntp * 16) * FPITCH + ks * 32 + hiK * 16);
                mma_h(sa[2 * ntp + 0], qf[ks], bf);
                mma_h(sa[2 * ntp + 1], qf[ks], bf + 2);
            }
        }

        if (ch + 1 < SEQ / 128) {
            const __half* Kn = Kp + (long)(ch + 1) * 128 * HIDDEN;
            const __half* Vn = Vp + (long)(ch + 1) * 128 * HIDDEN;
            uint32_t kdst = ksb + (buf ^ 1) * TILEB;
            uint32_t vdst = vsb + (buf ^ 1) * TILEB;
            #pragma unroll
            for (int i = 0; i < 4; i++) {
                int f = tid + i * 256; int r = f >> 3, u = f & 7;
                cp16(kdst + r * FPITCH + u * 16, Kn + (long)r * HIDDEN + u * 8);
                cp16(vdst + r * FPITCH + u * 16, Vn + (long)r * HIDDEN + u * 8);
            }
            cp_commit();
        }

        // online softmax: args fp32, exp in fp16x2 -> packed P is the A-frag
        float rmA = -1e30f, rmB = -1e30f;
        #pragma unroll
        for (int nt = 0; nt < 16; nt++) {
            rmA = fmaxf(rmA, fmaxf(sa[nt][0], sa[nt][1]));
            rmB = fmaxf(rmB, fmaxf(sa[nt][2], sa[nt][3]));
        }
        rmA = fmaxf(rmA, __shfl_xor_sync(0xffffffffu, rmA, 1));
        rmA = fmaxf(rmA, __shfl_xor_sync(0xffffffffu, rmA, 2));
        rmB = fmaxf(rmB, __shfl_xor_sync(0xffffffffu, rmB, 1));
        rmB = fmaxf(rmB, __shfl_xor_sync(0xffffffffu, rmB, 2));
        float mAn = fmaxf(mA, rmA), mBn = fmaxf(mB, rmB);
        float aA = ex2((mA - mAn) * LOG2E), aB = ex2((mB - mBn) * LOG2E);
        float mcA = mAn * LOG2E, mcB = mBn * LOG2E;
        uint32_t pp[16][2];
        float sA = 0.f, sB = 0.f;
        #pragma unroll
        for (int nt = 0; nt < 16; nt++) {
            float a0 = __fmaf_rn(sa[nt][0], LOG2E, -mcA);
            float a1 = __fmaf_rn(sa[nt][1], LOG2E, -mcA);
            float a2 = __fmaf_rn(sa[nt][2], LOG2E, -mcB);
            float a3 = __fmaf_rn(sa[nt][3], LOG2E, -mcB);
            uint32_t g01, g23;
            PACKH2(g01, a0, a1);
            PACKH2(g23, a2, a3);
            pp[nt][0] = ex2h2(g01);
            pp[nt][1] = ex2h2(g23);
            float2 f01 = __half22float2(*reinterpret_cast<__half2*>(&pp[nt][0]));
            float2 f23 = __half22float2(*reinterpret_cast<__half2*>(&pp[nt][1]));
            sA += f01.x + f01.y;
            sB += f23.x + f23.y;
        }
        sA += __shfl_xor_sync(0xffffffffu, sA, 1);
        sA += __shfl_xor_sync(0xffffffffu, sA, 2);
        sB += __shfl_xor_sync(0xffffffffu, sB, 1);
        sB += __shfl_xor_sync(0xffffffffu, sB, 2);
        lA = aA * lA + sA;  lB = aB * lB + sB;
        mA = mAn;  mB = mBn;
        #pragma unroll
        for (int nt = 0; nt < 8; nt++) {
            oa[nt][0] *= aA; oa[nt][1] *= aA;
            oa[nt][2] *= aB; oa[nt][3] *= aB;
        }

        // O += P @ V : pp IS the fp16 A-fragment set
        #pragma unroll
        for (int j = 0; j < 8; j++) {
            uint32_t af[4];
            af[0] = pp[2 * j][0];
            af[1] = pp[2 * j][1];
            af[2] = pp[2 * j + 1][0];
            af[3] = pp[2 * j + 1][1];
            #pragma unroll
            for (int dp = 0; dp < 4; dp++) {
                uint32_t bf[4];
                ldsm4t(bf, vbuf + (16 * j + rV) * FPITCH + dp * 32 + hiV * 16);
                mma_h(oa[2 * dp + 0], af, bf);
                mma_h(oa[2 * dp + 1], af, bf + 2);
            }
        }

        cp_wait0();
        __syncthreads();
    }

    float rA = 1.f / lA, rB = 1.f / lB;
    long rowA = tokbase + wid * 16 + qr;
    __half* OA = Og + rowA * HIDDEN + h * HEAD_DIM;
    __half* OB = OA + 8 * HIDDEN;
    #pragma unroll
    for (int nt = 0; nt < 8; nt++) {
        int col = nt * 8 + 2 * qc;
        *reinterpret_cast<__half2*>(OA + col) = __floats2half2_rn(oa[nt][0] * rA, oa[nt][1] * rA);
        *reinterpret_cast<__half2*>(OB + col) = __floats2half2_rn(oa[nt][2] * rB, oa[nt][3] * rB);
    }
}

// ---------------- fp16 GEMM, 128x128, BK=64, 2 CTAs/SM ----------------
// EPI: 1 -> fp32 +bias+resid out; 2 -> fp16 +bias+GELU out.
template<int EPI>
__global__ __launch_bounds__(256, 2)
void gemm_h(const __half* __restrict__ A, int lda,
            const __half* __restrict__ B, int ldb,
            void* __restrict__ Cv, int ldc, int K,
            const float* __restrict__ bias,
            const float* __restrict__ resid, int ldr)
{
    constexpr int MT = 4, NT = 4;
    constexpr int ABUF = 2 * TILEB;
    extern __shared__ char sm[];
    uint32_t sbase = smem_u32(sm);

    int tid = threadIdx.x, lane = tid & 31, wid = tid >> 5;
    int wr = wid >> 2, wc = wid & 3;
    int m0 = blockIdx.y * 128, n0 = blockIdx.x * 128;

    const __half* Ag = A + (long)m0 * lda;
    const __half* Bg = B + (long)n0 * ldb;

    int rA = wr * 64 + ((lane >> 3) & 1) * 8 + (lane & 7);
    int hiA = lane >> 4;
    int rB = wc * 32 + ((lane >> 4) & 1) * 8 + (lane & 7);
    int hiB = (lane >> 3) & 1;

    float acc[MT][NT][4];
    #pragma unroll
    for (int i = 0; i < MT; i++)
        #pragma unroll
        for (int j = 0; j < NT; j++)
            #pragma unroll
            for (int e = 0; e < 4; e++) acc[i][j][e] = 0.f;

    int nCh = K >> 6;

    #pragma unroll
    for (int i = 0; i < 4; i++) {
        int f = tid + i * 256; int r = f >> 3, u = f & 7;
        cp16(sbase + r * FPITCH + u * 16, Ag + (long)r * lda + u * 8);
        cp16(sbase + TILEB + r * FPITCH + u * 16, Bg + (long)r * ldb + u * 8);
    }
    cp_commit();

    for (int c = 0; c < nCh; ++c) {
        int buf = c & 1;
        cp_wait0();
        __syncthreads();
        if (c + 1 < nCh) {
            const __half* An = Ag + (c + 1) * 64;
            const __half* Bn = Bg + (c + 1) * 64;
            uint32_t dst = sbase + (buf ^ 1) * ABUF;
            #pragma unroll
            for (int i = 0; i < 4; i++) {
                int f = tid + i * 256; int r = f >> 3, u = f & 7;
                cp16(dst + r * FPITCH + u * 16, An + (long)r * lda + u * 8);
                cp16(dst + TILEB + r * FPITCH + u * 16, Bn + (long)r * ldb + u * 8);
            }
            cp_commit();
        }

        uint32_t aB = sbase + buf * ABUF;
        uint32_t bB = aB + TILEB;

        #pragma unroll
        for (int ks = 0; ks < 4; ++ks) {
            uint32_t af[MT][4], bf[NT / 2][4];
            #pragma unroll
            for (int mt = 0; mt < MT; mt++)
                ldsm4(af[mt], aB + (rA + mt * 16) * FPITCH + ks * 32 + hiA * 16);
            #pragma unroll
            for (int ntp = 0; ntp < NT / 2; ntp++)
                ldsm4(bf[ntp], bB + (rB + ntp * 16) * FPITCH + ks * 32 + hiB * 16);
            #pragma unroll
            for (int mt = 0; mt < MT; mt++)
                #pragma unroll
                for (int ntp = 0; ntp < NT / 2; ntp++) {
                    mma_h(acc[mt][2 * ntp + 0], af[mt], bf[ntp]);
                    mma_h(acc[mt][2 * ntp + 1], af[mt], bf[ntp] + 2);
                }
        }
        __syncthreads();
    }

    int qr = lane >> 2, qc = lane & 3;
    #pragma unroll
    for (int mt = 0; mt < MT; mt++) {
        #pragma unroll
        for (int half = 0; half < 2; half++) {
            int row = m0 + wr * 64 + mt * 16 + qr + half * 8;
            const float* Rrow = (EPI == 1) ? (resid + (long)row * ldr) : nullptr;
            #pragma unroll
            for (int nt = 0; nt < NT; nt++) {
                int col = n0 + wc * 32 + nt * 8 + 2 * qc;
                float v0 = acc[mt][nt][half * 2 + 0];
                float v1 = acc[mt][nt][half * 2 + 1];
                if (EPI == 1) {
                    v0 += bias[col]     + Rrow[col];
                    v1 += bias[col + 1] + Rrow[col + 1];
                    float* Crow = (float*)Cv + (long)row * ldc;
                    *reinterpret_cast<float2*>(&Crow[col]) = make_float2(v0, v1);
                } else {
                    v0 += bias[col];
                    v1 += bias[col + 1];
                    v0 = 0.5f * v0 * (1.0f + erff(v0 * 0.70710678118654752f));
                    v1 = 0.5f * v1 * (1.0f + erff(v1 * 0.70710678118654752f));
                    __half* Crow = (__half*)Cv + (long)row * ldc;
                    *reinterpret_cast<__half2*>(&Crow[col]) = __floats2half2_rn(v0, v1);
                }
            }
        }
    }
}

// ---------------- QKV GEMM: 3D grid, z selects weight/output; Q scaled 1/8 ----------------
__global__ __launch_bounds__(256, 2)
void gemm_qkv(const __half* __restrict__ A, int lda,
              const __half* __restrict__ Bw, __half* __restrict__ Cb, int K)
{
    constexpr int MT = 4, NT = 4;
    constexpr int ABUF = 2 * TILEB;
    extern __shared__ char sm[];
    uint32_t sbase = smem_u32(sm);

    int tid = threadIdx.x, lane = tid & 31, wid = tid >> 5;
    int wr = wid >> 2, wc = wid & 3;
    int zz = blockIdx.z;
    int m0 = blockIdx.y * 128, n0 = blockIdx.x * 128;
    float osc = (zz == 0) ? 0.125f : 1.0f;

    const __half* Ag = A + (long)m0 * lda;
    const __half* Bg = Bw + (long)zz * HIDDEN * HIDDEN + (long)n0 * HIDDEN;
    __half* C = Cb + (long)zz * MTOK * HIDDEN;

    int rA = wr * 64 + ((lane >> 3) & 1) * 8 + (lane & 7);
    int hiA = lane >> 4;
    int rB = wc * 32 + ((lane >> 4) & 1) * 8 + (lane & 7);
    int hiB = (lane >> 3) & 1;

    float acc[MT][NT][4];
    #pragma unroll
    for (int i = 0; i < MT; i++)
        #pragma unroll
        for (int j = 0; j < NT; j++)
            #pragma unroll
            for (int e = 0; e < 4; e++) acc[i][j][e] = 0.f;

    int nCh = K >> 6;

    #pragma unroll
    for (int i = 0; i < 4; i++) {
        int f = tid + i * 256; int r = f >> 3, u = f & 7;
        cp16(sbase + r * FPITCH + u * 16, Ag + (long)r * lda + u * 8);
        cp16(sbase + TILEB + r * FPITCH + u * 16, Bg + (long)r * HIDDEN + u * 8);
    }
    cp_commit();

    for (int c = 0; c < nCh; ++c) {
        int buf = c & 1;
        cp_wait0();
        __syncthreads();
        if (c + 1 < nCh) {
            const __half* An = Ag + (c + 1) * 64;
            const __half* Bn = Bg + (c + 1) * 64;
            uint32_t dst = sbase + (buf ^ 1) * ABUF;
            #pragma unroll
            for (int i = 0; i < 4; i++) {
                int f = tid + i * 256; int r = f >> 3, u = f & 7;
                cp16(dst + r * FPITCH + u * 16, An + (long)r * lda + u * 8);
                cp16(dst + TILEB + r * FPITCH + u * 16, Bn + (long)r * HIDDEN + u * 8);
            }
            cp_commit();
        }

        uint32_t aB = sbase + buf * ABUF;
        uint32_t bB = aB + TILEB;

        #pragma unroll
        for (int ks = 0; ks < 4; ++ks) {
            uint32_t af[MT][4], bf[NT / 2][4];
            #pragma unroll
            for (int mt = 0; mt < MT; mt++)
                ldsm4(af[mt], aB + (rA + mt * 16) * FPITCH + ks * 32 + hiA * 16);
            #pragma unroll
            for (int ntp = 0; ntp < NT / 2; ntp++)
                ldsm4(bf[ntp], bB + (rB + ntp * 16) * FPITCH + ks * 32 + hiB * 16);
            #pragma unroll
            for (int mt = 0; mt < MT; mt++)
                #pragma unroll
                for (int ntp = 0; ntp < NT / 2; ntp++) {
                    mma_h(acc[mt][2 * ntp + 0], af[mt], bf[ntp]);
                    mma_h(acc[mt][2 * ntp + 1], af[mt], bf[ntp] + 2);
                }
        }
        __syncthreads();
    }

    int qr = lane >> 2, qc = lane & 3;
    #pragma unroll
    for (int mt = 0; mt < MT; mt++) {
        #pragma unroll
        for (int half = 0; half < 2; half++) {
            int row = m0 + wr * 64 + mt * 16 + qr + half * 8;
            __half* Crow = C + (long)row * HIDDEN;
            #pragma unroll
            for (int nt = 0; nt < NT; nt++) {
                int col = n0 + wc * 32 + nt * 8 + 2 * qc;
                float v0 = acc[mt][nt][half * 2 + 0] * osc;
                float v1 = acc[mt][nt][half * 2 + 1] * osc;
                *reinterpret_cast<__half2*>(&Crow[col]) = __floats2half2_rn(v0, v1);
            }
        }
    }
}

// ---------------- launcher ----------------
extern "C" void kernel_launch(void* const* d_in, const int* in_sizes, int n_in,
                              void* d_out, int out_size)
{
    const float* x    = (const float*)d_in[0];
    const float* ln1g = (const float*)d_in[1];
    const float* ln1b = (const float*)d_in[2];
    const float* wq   = (const float*)d_in[3];
    const float* wk   = (const float*)d_in[4];
    const float* wv   = (const float*)d_in[5];
    const float* wo   = (const float*)d_in[6];
    const float* bo   = (const float*)d_in[7];
    const float* ln2g = (const float*)d_in[8];
    const float* ln2b = (const float*)d_in[9];
    const float* w1   = (const float*)d_in[10];
    const float* b1   = (const float*)d_in[11];
    const float* w2   = (const float*)d_in[12];
    const float* b2   = (const float*)d_in[13];
    float* out = (float*)d_out;

    __half *xn, *qkv, *attn, *hm, *w1t, *w2t, *rwqkv, *rwo;
    float* x1;
    cudaGetSymbolAddress((void**)&xn,    g_xn);
    cudaGetSymbolAddress((void**)&qkv,   g_qkv);
    cudaGetSymbolAddress((void**)&attn,  g_attn);
    cudaGetSymbolAddress((void**)&x1,    g_x1);
    cudaGetSymbolAddress((void**)&hm,    g_h);
    cudaGetSymbolAddress((void**)&w1t,   g_w1t);
    cudaGetSymbolAddress((void**)&w2t,   g_w2t);
    cudaGetSymbolAddress((void**)&rwqkv, g_wqkv);
    cudaGetSymbolAddress((void**)&rwo,   g_wo);

    __half* qb = qkv;
    __half* kb = qkv + (size_t)MTOK * HIDDEN;
    __half* vb = qkv + (size_t)2 * MTOK * HIDDEN;

    const int SMGE = 4 * TILEB;                 // 73728
    const int SMFL = 5 * TILEB;                 // 92160
    cudaFuncSetAttribute((const void*)gemm_h<1>, cudaFuncAttributeMaxDynamicSharedMemorySize, SMGE);
    cudaFuncSetAttribute((const void*)gemm_h<2>, cudaFuncAttributeMaxDynamicSharedMemorySize, SMGE);
    cudaFuncSetAttribute((const void*)gemm_qkv,  cudaFuncAttributeMaxDynamicSharedMemorySize, SMGE);
    cudaFuncSetAttribute((const void*)flash_k,   cudaFuncAttributeMaxDynamicSharedMemorySize, SMFL);

    // prep: 3 launches
    int nw = HIDDEN * HIDDEN / 4;
    wpack_k<<<(4 * nw + 255) / 256, 256>>>(wq, wk, wv, wo, rwqkv, rwo);
    transpose_k<<<dim3(MLPH / 32, HIDDEN / 32), 256>>>(w1, MLPH, w1t, HIDDEN);
    transpose_k<<<dim3(HIDDEN / 32, MLPH / 32), 256>>>(w2, HIDDEN, w2t, MLPH);

    // 1. LN1
    ln_k<<<MTOK, 256>>>(x, ln1g, ln1b, xn);

    // 2. QKV: one 3D launch (Q pre-scaled by 1/8)
    gemm_qkv<<<dim3(HIDDEN / 128, MTOK / 128, 3), 256, SMGE>>>(xn, HIDDEN, rwqkv, qkv, HIDDEN);

    // 3. fused attention
    flash_k<<<dim3(SEQ / 128, BATCH * HEADS), 256, SMFL>>>(qb, kb, vb, attn);

    // 4. x1 = attn @ wo^T + bo + x
    dim3 gH(HIDDEN / 128, MTOK / 128);
    gemm_h<1><<<gH, 256, SMGE>>>(attn, HIDDEN, rwo, HIDDEN, x1, HIDDEN, HIDDEN, bo, x, HIDDEN);

    // 5. LN2
    ln_k<<<MTOK, 256>>>(x1, ln2g, ln2b, xn);

    // 6. h = gelu(xn @ w1 + b1)   (128x128, 2 CTAs/SM)
    gemm_h<2><<<dim3(MLPH / 128, MTOK / 128), 256, SMGE>>>(
        xn, HIDDEN, w1t, HIDDEN, hm, MLPH, HIDDEN, b1, nullptr, 0);

    // 7. out = h @ w2 + b2 + x1   (128x128, 2 CTAs/SM)
    gemm_h<1><<<gH, 256, SMGE>>>(hm, MLPH, w2t, MLPH, out, HIDDEN, MLPH, b2, x1, HIDDEN);
}

// round 14
// speedup vs baseline: 1.0496x; 1.0188x over previous
#include <cuda_runtime.h>
#include <cuda_fp16.h>
#include <math.h>
#include <stdint.h>

// ---------------- problem constants ----------------
#define HIDDEN   768
#define MLPH     3072
#define HEADS    12
#define HEAD_DIM 64
#define BATCH    16
#define SEQ      1024
#define MTOK     (BATCH * SEQ)

// ---------------- scratch ----------------
__device__ __align__(16) __half g_xn  [(size_t)MTOK * HIDDEN];
__device__ __align__(16) __half g_qkv [(size_t)3 * MTOK * HIDDEN];
__device__ __align__(16) __half g_attn[(size_t)MTOK * HIDDEN];
__device__ __align__(16) float  g_x1  [(size_t)MTOK * HIDDEN];
__device__ __align__(16) __half g_h   [(size_t)MTOK * MLPH];
__device__ __align__(16) __half g_w1t [(size_t)MLPH * HIDDEN];
__device__ __align__(16) __half g_w2t [(size_t)HIDDEN * MLPH];
__device__ __align__(16) __half g_wqkv[(size_t)3 * HIDDEN * HIDDEN];
__device__ __align__(16) __half g_wo  [(size_t)HIDDEN * HIDDEN];

// ---------------- helpers ----------------
__device__ __forceinline__ uint32_t smem_u32(const void* p) {
    uint32_t a;
    asm("{ .reg .u64 t; cvta.to.shared.u64 t, %1; cvt.u32.u64 %0, t; }" : "=r"(a) : "l"(p));
    return a;
}
__device__ __forceinline__ void ldsm4(uint32_t* r, uint32_t addr) {
    asm volatile("ldmatrix.sync.aligned.m8n8.x4.shared.b16 {%0,%1,%2,%3}, [%4];"
                 : "=r"(r[0]), "=r"(r[1]), "=r"(r[2]), "=r"(r[3]) : "r"(addr));
}
__device__ __forceinline__ void ldsm4t(uint32_t* r, uint32_t addr) {
    asm volatile("ldmatrix.sync.aligned.m8n8.x4.trans.shared.b16 {%0,%1,%2,%3}, [%4];"
                 : "=r"(r[0]), "=r"(r[1]), "=r"(r[2]), "=r"(r[3]) : "r"(addr));
}
__device__ __forceinline__ void cp16(uint32_t saddr, const void* g) {
    asm volatile("cp.async.ca.shared.global [%0], [%1], 16;" :: "r"(saddr), "l"(g) : "memory");
}
__device__ __forceinline__ void cp_commit() {
    asm volatile("cp.async.commit_group;" ::: "memory");
}
__device__ __forceinline__ void cp_wait0() {
    asm volatile("cp.async.wait_group 0;" ::: "memory");
}
__device__ __forceinline__ void mma_h(float* d, const uint32_t* a, const uint32_t* b) {
    asm volatile("mma.sync.aligned.m16n8k16.row.col.f32.f16.f16.f32 "
                 "{%0,%1,%2,%3}, {%4,%5,%6,%7}, {%8,%9}, {%0,%1,%2,%3};"
                 : "+f"(d[0]), "+f"(d[1]), "+f"(d[2]), "+f"(d[3])
                 : "r"(a[0]), "r"(a[1]), "r"(a[2]), "r"(a[3]), "r"(b[0]), "r"(b[1]));
}
__device__ __forceinline__ float ex2(float x) {
    float r; asm("ex2.approx.f32 %0, %1;" : "=f"(r) : "f"(x)); return r;
}
#define PACKH2(r, lo, hi) \
    asm("cvt.rn.f16x2.f32 %0, %1, %2;" : "=r"(r) : "f"(hi), "f"(lo))
__device__ __forceinline__ uint32_t ex2h2(uint32_t a) {
    uint32_t r; asm("ex2.approx.f16x2 %0, %1;" : "=r"(r) : "r"(a)); return r;
}
__device__ __forceinline__ float warp_sum(float v) {
    #pragma unroll
    for (int o = 16; o; o >>= 1) v += __shfl_xor_sync(0xffffffffu, v, o);
    return v;
}

// ---------------- prep: round/pack all 4 hidden-square weights ----------------
__global__ __launch_bounds__(256)
void wpack_k(const float* __restrict__ wq, const float* __restrict__ wk,
             const float* __restrict__ wv, const float* __restrict__ wo,
             __half* __restrict__ dqkv, __half* __restrict__ dwo)
{
    const int N4 = HIDDEN * HIDDEN / 4;
    int i = blockIdx.x * 256 + threadIdx.x;
    if (i >= 4 * N4) return;
    int seg = i / N4, j = i - seg * N4;
    const float* src = (seg == 0) ? wq : (seg == 1) ? wk : (seg == 2) ? wv : wo;
    __half* dst = (seg == 3) ? dwo : dqkv + (size_t)seg * HIDDEN * HIDDEN;
    float4 v = reinterpret_cast<const float4*>(src)[j];
    __half2* d = reinterpret_cast<__half2*>(dst);
    d[2 * j + 0] = __floats2half2_rn(v.x, v.y);
    d[2 * j + 1] = __floats2half2_rn(v.z, v.w);
}

// ---------------- LayerNorm: warp per row, float4, no smem ----------------
__global__ __launch_bounds__(256)
void ln_k(const float* __restrict__ x, const float* __restrict__ g,
          const float* __restrict__ b, __half* __restrict__ out)
{
    int lane = threadIdx.x & 31, w = threadIdx.x >> 5;
    long row = (long)blockIdx.x * 8 + w;
    const float* xr = x + row * (long)HIDDEN;

    float4 v[6];
    float s = 0.f, s2 = 0.f;
    #pragma unroll
    for (int i = 0; i < 6; i++) {
        v[i] = *reinterpret_cast<const float4*>(xr + i * 128 + lane * 4);
        s  += v[i].x + v[i].y + v[i].z + v[i].w;
        s2 += v[i].x * v[i].x + v[i].y * v[i].y + v[i].z * v[i].z + v[i].w * v[i].w;
    }
    s = warp_sum(s); s2 = warp_sum(s2);
    float mu  = s * (1.0f / HIDDEN);
    float var = s2 * (1.0f / HIDDEN) - mu * mu;
    float rstd = rsqrtf(var + 1e-5f);

    __half* o = out + row * (long)HIDDEN;
    #pragma unroll
    for (int i = 0; i < 6; i++) {
        int col = i * 128 + lane * 4;
        float4 gg = *reinterpret_cast<const float4*>(g + col);
        float4 bb = *reinterpret_cast<const float4*>(b + col);
        __half2 h0 = __floats2half2_rn((v[i].x - mu) * rstd * gg.x + bb.x,
                                       (v[i].y - mu) * rstd * gg.y + bb.y);
        __half2 h1 = __floats2half2_rn((v[i].z - mu) * rstd * gg.z + bb.z,
                                       (v[i].w - mu) * rstd * gg.w + bb.w);
        uint2 st;
        st.x = *reinterpret_cast<uint32_t*>(&h0);
        st.y = *reinterpret_cast<uint32_t*>(&h1);
        *reinterpret_cast<uint2*>(o + col) = st;
    }
}

// ---------------- merged weight transposes (z: 0 -> w1, 1 -> w2) ----------------
__global__ __launch_bounds__(256)
void transpose2_k(const float* __restrict__ w1, const float* __restrict__ w2,
                  __half* __restrict__ w1t, __half* __restrict__ w2t)
{
    __shared__ float t[32][33];
    int zz = blockIdx.z;
    const float* in  = zz ? w2 : w1;
    __half* out      = zz ? w2t : w1t;
    int ldi = zz ? HIDDEN : MLPH;
    int ldo = zz ? MLPH : HIDDEN;
    int bx = zz ? blockIdx.y : blockIdx.x;    // column-block of input
    int by = zz ? blockIdx.x : blockIdx.y;    // row-block of input
    int c0 = bx * 32, r0 = by * 32;
    int tx = threadIdx.x & 31, ty = threadIdx.x >> 5;
    #pragma unroll
    for (int i = ty; i < 32; i += 8)
        t[i][tx] = in[(long)(r0 + i) * ldi + c0 + tx];
    __syncthreads();
    #pragma unroll
    for (int i = ty; i < 32; i += 8)
        out[(long)(c0 + i) * ldo + r0 + tx] = __float2half_rn(t[tx][i]);
}

#define FPITCH 144
#define TILEB  (128 * FPITCH)       // 18432
#define KCH    (2 * TILEB)          // 256-row K/V buffer
#define LOG2E  1.4426950408889634f

// ---------------- flash attention (fp16; 256-key chunks, 2 halves/iter) ----------------
__global__ __launch_bounds__(256)
void flash_k(const __half* __restrict__ Qb, const __half* __restrict__ Kb,
             const __half* __restrict__ Vg, __half* __restrict__ Og)
{
    extern __shared__ char sm[];
    uint32_t qsb = smem_u32(sm);
    uint32_t ksb = qsb + TILEB;          // 2 buffers x 256 rows
    uint32_t vsb = ksb + 2 * KCH;        // 2 buffers x 256 rows

    int tid = threadIdx.x, lane = tid & 31, wid = tid >> 5;
    int qr = lane >> 2, qc = lane & 3;
    int z = blockIdx.y;
    int b = z / HEADS, h = z - b * HEADS;
    int q0 = blockIdx.x * 128;
    long tokbase = (long)b * SEQ + q0;

    const __half* Qp = Qb + tokbase * HIDDEN + h * HEAD_DIM;
    const __half* Kp = Kb + (long)b * SEQ * HIDDEN + h * HEAD_DIM;
    const __half* Vp = Vg + (long)b * SEQ * HIDDEN + h * HEAD_DIM;

    // prologue: Q (128 rows) + K0/V0 (256 rows each)
    #pragma unroll
    for (int i = 0; i < 4; i++) {
        int f = tid + i * 256; int r = f >> 3, u = f & 7;
        cp16(qsb + r * FPITCH + u * 16, Qp + (long)r * HIDDEN + u * 8);
    }
    #pragma unroll
    for (int i = 0; i < 8; i++) {
        int f = tid + i * 256; int r = f >> 3, u = f & 7;
        cp16(ksb + r * FPITCH + u * 16, Kp + (long)r * HIDDEN + u * 8);
        cp16(vsb + r * FPITCH + u * 16, Vp + (long)r * HIDDEN + u * 8);
    }
    cp_commit();
    cp_wait0();
    __syncthreads();

    int rQ = wid * 16 + ((lane >> 3) & 1) * 8 + (lane & 7);
    int hiQ = lane >> 4;
    uint32_t qf[4][4];
    #pragma unroll
    for (int ks = 0; ks < 4; ks++)
        ldsm4(qf[ks], qsb + rQ * FPITCH + ks * 32 + hiQ * 16);

    int rK = ((lane >> 4) & 1) * 8 + (lane & 7);
    int hiK = (lane >> 3) & 1;
    int rV = ((lane >> 3) & 1) * 8 + (lane & 7);
    int hiV = lane >> 4;

    float oa[8][4];
    #pragma unroll
    for (int i = 0; i < 8; i++)
        #pragma unroll
        for (int e = 0; e < 4; e++) oa[i][e] = 0.f;
    float mA = -1e30f, mB = -1e30f, lA = 0.f, lB = 0.f;

    const int NCH = SEQ / 256;   // 4
    for (int ch = 0; ch < NCH; ch++) {
        int buf = ch & 1;

        // prefetch next 256-row K/V into other buffers (overlaps both halves)
        if (ch + 1 < NCH) {
            const __half* Kn = Kp + (long)(ch + 1) * 256 * HIDDEN;
            const __half* Vn = Vp + (long)(ch + 1) * 256 * HIDDEN;
            uint32_t kdst = ksb + (buf ^ 1) * KCH;
            uint32_t vdst = vsb + (buf ^ 1) * KCH;
            #pragma unroll
            for (int i = 0; i < 8; i++) {
                int f = tid + i * 256; int r = f >> 3, u = f & 7;
                cp16(kdst + r * FPITCH + u * 16, Kn + (long)r * HIDDEN + u * 8);
                cp16(vdst + r * FPITCH + u * 16, Vn + (long)r * HIDDEN + u * 8);
            }
            cp_commit();
        }

        #pragma unroll
        for (int p = 0; p < 2; p++) {
            uint32_t kbuf = ksb + buf * KCH + p * TILEB;
            uint32_t vbuf = vsb + buf * KCH + p * TILEB;

            // S = Q @ K^T (Q pre-scaled by 1/8)
            float sa[16][4];
            #pragma unroll
            for (int i = 0; i < 16; i++)
                #pragma unroll
                for (int e = 0; e < 4; e++) sa[i][e] = 0.f;
            #pragma unroll
            for (int ks = 0; ks < 4; ks++) {
                #pragma unroll
                for (int ntp = 0; ntp < 8; ntp++) {
                    uint32_t bf[4];
                    ldsm4(bf, kbuf + (rK + ntp * 16) * FPITCH + ks * 32 + hiK * 16);
                    mma_h(sa[2 * ntp + 0], qf[ks], bf);
                    mma_h(sa[2 * ntp + 1], qf[ks], bf + 2);
                }
            }

            // online softmax (fp32 args, fp16x2 exp)
            float rmA = -1e30f, rmB = -1e30f;
            #pragma unroll
            for (int nt = 0; nt < 16; nt++) {
                rmA = fmaxf(rmA, fmaxf(sa[nt][0], sa[nt][1]));
                rmB = fmaxf(rmB, fmaxf(sa[nt][2], sa[nt][3]));
            }
            rmA = fmaxf(rmA, __shfl_xor_sync(0xffffffffu, rmA, 1));
            rmA = fmaxf(rmA, __shfl_xor_sync(0xffffffffu, rmA, 2));
            rmB = fmaxf(rmB, __shfl_xor_sync(0xffffffffu, rmB, 1));
            rmB = fmaxf(rmB, __shfl_xor_sync(0xffffffffu, rmB, 2));
            float mAn = fmaxf(mA, rmA), mBn = fmaxf(mB, rmB);
            float aA = ex2((mA - mAn) * LOG2E), aB = ex2((mB - mBn) * LOG2E);
            float mcA = mAn * LOG2E, mcB = mBn * LOG2E;
            uint32_t pp[16][2];
            float sA = 0.f, sB = 0.f;
            #pragma unroll
            for (int nt = 0; nt < 16; nt++) {
                float a0 = __fmaf_rn(sa[nt][0], LOG2E, -mcA);
                float a1 = __fmaf_rn(sa[nt][1], LOG2E, -mcA);
                float a2 = __fmaf_rn(sa[nt][2], LOG2E, -mcB);
                float a3 = __fmaf_rn(sa[nt][3], LOG2E, -mcB);
                uint32_t g01, g23;
                PACKH2(g01, a0, a1);
                PACKH2(g23, a2, a3);
                pp[nt][0] = ex2h2(g01);
                pp[nt][1] = ex2h2(g23);
                float2 f01 = __half22float2(*reinterpret_cast<__half2*>(&pp[nt][0]));
                float2 f23 = __half22float2(*reinterpret_cast<__half2*>(&pp[nt][1]));
                sA += f01.x + f01.y;
                sB += f23.x + f23.y;
            }
            sA += __shfl_xor_sync(0xffffffffu, sA, 1);
            sA += __shfl_xor_sync(0xffffffffu, sA, 2);
            sB += __shfl_xor_sync(0xffffffffu, sB, 1);
            sB += __shfl_xor_sync(0xffffffffu, sB, 2);
            lA = aA * lA + sA;  lB = aB * lB + sB;
            mA = mAn;  mB = mBn;
            #pragma unroll
            for (int nt = 0; nt < 8; nt++) {
                oa[nt][0] *= aA; oa[nt][1] *= aA;
                oa[nt][2] *= aB; oa[nt][3] *= aB;
            }

            // O += P @ V
            #pragma unroll
            for (int j = 0; j < 8; j++) {
                uint32_t af[4];
                af[0] = pp[2 * j][0];
                af[1] = pp[2 * j][1];
                af[2] = pp[2 * j + 1][0];
                af[3] = pp[2 * j + 1][1];
                #pragma unroll
                for (int dp = 0; dp < 4; dp++) {
                    uint32_t bf[4];
                    ldsm4t(bf, vbuf + (16 * j + rV) * FPITCH + dp * 32 + hiV * 16);
                    mma_h(oa[2 * dp + 0], af, bf);
                    mma_h(oa[2 * dp + 1], af, bf + 2);
                }
            }
        }

        cp_wait0();
        __syncthreads();
    }

    float rA = 1.f / lA, rB = 1.f / lB;
    long rowA = tokbase + wid * 16 + qr;
    __half* OA = Og + rowA * HIDDEN + h * HEAD_DIM;
    __half* OB = OA + 8 * HIDDEN;
    #pragma unroll
    for (int nt = 0; nt < 8; nt++) {
        int col = nt * 8 + 2 * qc;
        *reinterpret_cast<__half2*>(OA + col) = __floats2half2_rn(oa[nt][0] * rA, oa[nt][1] * rA);
        *reinterpret_cast<__half2*>(OB + col) = __floats2half2_rn(oa[nt][2] * rB, oa[nt][3] * rB);
    }
}

// ---------------- fp16 GEMM, 128x128, BK=64, 2 CTAs/SM ----------------
// EPI: 1 -> fp32 +bias+resid out; 2 -> fp16 +bias+GELU out.
template<int EPI>
__global__ __launch_bounds__(256, 2)
void gemm_h(const __half* __restrict__ A, int lda,
            const __half* __restrict__ B, int ldb,
            void* __restrict__ Cv, int ldc, int K,
            const float* __restrict__ bias,
            const float* __restrict__ resid, int ldr)
{
    constexpr int MT = 4, NT = 4;
    constexpr int ABUF = 2 * TILEB;
    extern __shared__ char sm[];
    uint32_t sbase = smem_u32(sm);

    int tid = threadIdx.x, lane = tid & 31, wid = tid >> 5;
    int wr = wid >> 2, wc = wid & 3;
    int m0 = blockIdx.y * 128, n0 = blockIdx.x * 128;

    const __half* Ag = A + (long)m0 * lda;
    const __half* Bg = B + (long)n0 * ldb;

    int rA = wr * 64 + ((lane >> 3) & 1) * 8 + (lane & 7);
    int hiA = lane >> 4;
    int rB = wc * 32 + ((lane >> 4) & 1) * 8 + (lane & 7);
    int hiB = (lane >> 3) & 1;

    float acc[MT][NT][4];
    #pragma unroll
    for (int i = 0; i < MT; i++)
        #pragma unroll
        for (int j = 0; j < NT; j++)
            #pragma unroll
            for (int e = 0; e < 4; e++) acc[i][j][e] = 0.f;

    int nCh = K >> 6;

    #pragma unroll
    for (int i = 0; i < 4; i++) {
        int f = tid + i * 256; int r = f >> 3, u = f & 7;
        cp16(sbase + r * FPITCH + u * 16, Ag + (long)r * lda + u * 8);
        cp16(sbase + TILEB + r * FPITCH + u * 16, Bg + (long)r * ldb + u * 8);
    }
    cp_commit();

    for (int c = 0; c < nCh; ++c) {
        int buf = c & 1;
        cp_wait0();
        __syncthreads();
        if (c + 1 < nCh) {
            const __half* An = Ag + (c + 1) * 64;
            const __half* Bn = Bg + (c + 1) * 64;
            uint32_t dst = sbase + (buf ^ 1) * ABUF;
            #pragma unroll
            for (int i = 0; i < 4; i++) {
                int f = tid + i * 256; int r = f >> 3, u = f & 7;
                cp16(dst + r * FPITCH + u * 16, An + (long)r * lda + u * 8);
                cp16(dst + TILEB + r * FPITCH + u * 16, Bn + (long)r * ldb + u * 8);
            }
            cp_commit();
        }

        uint32_t aB = sbase + buf * ABUF;
        uint32_t bB = aB + TILEB;

        #pragma unroll
        for (int ks = 0; ks < 4; ++ks) {
            uint32_t af[MT][4], bf[NT / 2][4];
            #pragma unroll
            for (int mt = 0; mt < MT; mt++)
                ldsm4(af[mt], aB + (rA + mt * 16) * FPITCH + ks * 32 + hiA * 16);
            #pragma unroll
            for (int ntp = 0; ntp < NT / 2; ntp++)
                ldsm4(bf[ntp], bB + (rB + ntp * 16) * FPITCH + ks * 32 + hiB * 16);
            #pragma unroll
            for (int mt = 0; mt < MT; mt++)
                #pragma unroll
                for (int ntp = 0; ntp < NT / 2; ntp++) {
                    mma_h(acc[mt][2 * ntp + 0], af[mt], bf[ntp]);
                    mma_h(acc[mt][2 * ntp + 1], af[mt], bf[ntp] + 2);
                }
        }
        __syncthreads();
    }

    int qr = lane >> 2, qc = lane & 3;
    #pragma unroll
    for (int mt = 0; mt < MT; mt++) {
        #pragma unroll
        for (int half = 0; half < 2; half++) {
            int row = m0 + wr * 64 + mt * 16 + qr + half * 8;
            const float* Rrow = (EPI == 1) ? (resid + (long)row * ldr) : nullptr;
            #pragma unroll
            for (int nt = 0; nt < NT; nt++) {
                int col = n0 + wc * 32 + nt * 8 + 2 * qc;
                float v0 = acc[mt][nt][half * 2 + 0];
                float v1 = acc[mt][nt][half * 2 + 1];
                if (EPI == 1) {
                    v0 += bias[col]     + Rrow[col];
                    v1 += bias[col + 1] + Rrow[col + 1];
                    float* Crow = (float*)Cv + (long)row * ldc;
                    *reinterpret_cast<float2*>(&Crow[col]) = make_float2(v0, v1);
                } else {
                    v0 += bias[col];
                    v1 += bias[col + 1];
                    v0 = 0.5f * v0 * (1.0f + erff(v0 * 0.70710678118654752f));
                    v1 = 0.5f * v1 * (1.0f + erff(v1 * 0.70710678118654752f));
                    __half* Crow = (__half*)Cv + (long)row * ldc;
                    *reinterpret_cast<__half2*>(&Crow[col]) = __floats2half2_rn(v0, v1);
                }
            }
        }
    }
}

// ---------------- QKV GEMM: 3D grid, z selects weight/output; Q scaled 1/8 ----------------
__global__ __launch_bounds__(256, 2)
void gemm_qkv(const __half* __restrict__ A, int lda,
              const __half* __restrict__ Bw, __half* __restrict__ Cb, int K)
{
    constexpr int MT = 4, NT = 4;
    constexpr int ABUF = 2 * TILEB;
    extern __shared__ char sm[];
    uint32_t sbase = smem_u32(sm);

    int tid = threadIdx.x, lane = tid & 31, wid = tid >> 5;
    int wr = wid >> 2, wc = wid & 3;
    int zz = blockIdx.z;
    int m0 = blockIdx.y * 128, n0 = blockIdx.x * 128;
    float osc = (zz == 0) ? 0.125f : 1.0f;

    const __half* Ag = A + (long)m0 * lda;
    const __half* Bg = Bw + (long)zz * HIDDEN * HIDDEN + (long)n0 * HIDDEN;
    __half* C = Cb + (long)zz * MTOK * HIDDEN;

    int rA = wr * 64 + ((lane >> 3) & 1) * 8 + (lane & 7);
    int hiA = lane >> 4;
    int rB = wc * 32 + ((lane >> 4) & 1) * 8 + (lane & 7);
    int hiB = (lane >> 3) & 1;

    float acc[MT][NT][4];
    #pragma unroll
    for (int i = 0; i < MT; i++)
        #pragma unroll
        for (int j = 0; j < NT; j++)
            #pragma unroll
            for (int e = 0; e < 4; e++) acc[i][j][e] = 0.f;

    int nCh = K >> 6;

    #pragma unroll
    for (int i = 0; i < 4; i++) {
        int f = tid + i * 256; int r = f >> 3, u = f & 7;
        cp16(sbase + r * FPITCH + u * 16, Ag + (long)r * lda + u * 8);
        cp16(sbase + TILEB + r * FPITCH + u * 16, Bg + (long)r * HIDDEN + u * 8);
    }
    cp_commit();

    for (int c = 0; c < nCh; ++c) {
        int buf = c & 1;
        cp_wait0();
        __syncthreads();
        if (c + 1 < nCh) {
            const __half* An = Ag + (c + 1) * 64;
            const __half* Bn = Bg + (c + 1) * 64;
            uint32_t dst = sbase + (buf ^ 1) * ABUF;
            #pragma unroll
            for (int i = 0; i < 4; i++) {
                int f = tid + i * 256; int r = f >> 3, u = f & 7;
                cp16(dst + r * FPITCH + u * 16, An + (long)r * lda + u * 8);
                cp16(dst + TILEB + r * FPITCH + u * 16, Bn + (long)r * HIDDEN + u * 8);
            }
            cp_commit();
        }

        uint32_t aB = sbase + buf * ABUF;
        uint32_t bB = aB + TILEB;

        #pragma unroll
        for (int ks = 0; ks < 4; ++ks) {
            uint32_t af[MT][4], bf[NT / 2][4];
            #pragma unroll
            for (int mt = 0; mt < MT; mt++)
                ldsm4(af[mt], aB + (rA + mt * 16) * FPITCH + ks * 32 + hiA * 16);
            #pragma unroll
            for (int ntp = 0; ntp < NT / 2; ntp++)
                ldsm4(bf[ntp], bB + (rB + ntp * 16) * FPITCH + ks * 32 + hiB * 16);
            #pragma unroll
            for (int mt = 0; mt < MT; mt++)
                #pragma unroll
                for (int ntp = 0; ntp < NT / 2; ntp++) {
                    mma_h(acc[mt][2 * ntp + 0], af[mt], bf[ntp]);
                    mma_h(acc[mt][2 * ntp + 1], af[mt], bf[ntp] + 2);
                }
        }
        __syncthreads();
    }

    int qr = lane >> 2, qc = lane & 3;
    #pragma unroll
    for (int mt = 0; mt < MT; mt++) {
        #pragma unroll
        for (int half = 0; half < 2; half++) {
            int row = m0 + wr * 64 + mt * 16 + qr + half * 8;
            __half* Crow = C + (long)row * HIDDEN;
            #pragma unroll
            for (int nt = 0; nt < NT; nt++) {
                int col = n0 + wc * 32 + nt * 8 + 2 * qc;
                float v0 = acc[mt][nt][half * 2 + 0] * osc;
                float v1 = acc[mt][nt][half * 2 + 1] * osc;
                *reinterpret_cast<__half2*>(&Crow[col]) = __floats2half2_rn(v0, v1);
            }
        }
    }
}

// ---------------- launcher ----------------
extern "C" void kernel_launch(void* const* d_in, const int* in_sizes, int n_in,
                              void* d_out, int out_size)
{
    const float* x    = (const float*)d_in[0];
    const float* ln1g = (const float*)d_in[1];
    const float* ln1b = (const float*)d_in[2];
    const float* wq   = (const float*)d_in[3];
    const float* wk   = (const float*)d_in[4];
    const float* wv   = (const float*)d_in[5];
    const float* wo   = (const float*)d_in[6];
    const float* bo   = (const float*)d_in[7];
    const float* ln2g = (const float*)d_in[8];
    const float* ln2b = (const float*)d_in[9];
    const float* w1   = (const float*)d_in[10];
    const float* b1   = (const float*)d_in[11];
    const float* w2   = (const float*)d_in[12];
    const float* b2   = (const float*)d_in[13];
    float* out = (float*)d_out;

    __half *xn, *qkv, *attn, *hm, *w1t, *w2t, *rwqkv, *rwo;
    float* x1;
    cudaGetSymbolAddress((void**)&xn,    g_xn);
    cudaGetSymbolAddress((void**)&qkv,   g_qkv);
    cudaGetSymbolAddress((void**)&attn,  g_attn);
    cudaGetSymbolAddress((void**)&x1,    g_x1);
    cudaGetSymbolAddress((void**)&hm,    g_h);
    cudaGetSymbolAddress((void**)&w1t,   g_w1t);
    cudaGetSymbolAddress((void**)&w2t,   g_w2t);
    cudaGetSymbolAddress((void**)&rwqkv, g_wqkv);
    cudaGetSymbolAddress((void**)&rwo,   g_wo);

    __half* qb = qkv;
    __half* kb = qkv + (size_t)MTOK * HIDDEN;
    __half* vb = qkv + (size_t)2 * MTOK * HIDDEN;

    const int SMGE = 4 * TILEB;                 // 73728
    const int SMFL = TILEB + 4 * KCH;           // 165888: Q + 2x256K + 2x256V
    cudaFuncSetAttribute((const void*)gemm_h<1>, cudaFuncAttributeMaxDynamicSharedMemorySize, SMGE);
    cudaFuncSetAttribute((const void*)gemm_h<2>, cudaFuncAttributeMaxDynamicSharedMemorySize, SMGE);
    cudaFuncSetAttribute((const void*)gemm_qkv,  cudaFuncAttributeMaxDynamicSharedMemorySize, SMGE);
    cudaFuncSetAttribute((const void*)flash_k,   cudaFuncAttributeMaxDynamicSharedMemorySize, SMFL);

    // prep: 2 launches
    int nw = HIDDEN * HIDDEN / 4;
    wpack_k<<<(4 * nw + 255) / 256, 256>>>(wq, wk, wv, wo, rwqkv, rwo);
    transpose2_k<<<dim3(MLPH / 32, HIDDEN / 32, 2), 256>>>(w1, w2, w1t, w2t);

    // 1. LN1 (warp-per-row)
    ln_k<<<MTOK / 8, 256>>>(x, ln1g, ln1b, xn);

    // 2. QKV: one 3D launch (Q pre-scaled by 1/8)
    gemm_qkv<<<dim3(HIDDEN / 128, MTOK / 128, 3), 256, SMGE>>>(xn, HIDDEN, rwqkv, qkv, HIDDEN);

    // 3. fused attention (256-key chunks)
    flash_k<<<dim3(SEQ / 128, BATCH * HEADS), 256, SMFL>>>(qb, kb, vb, attn);

    // 4. x1 = attn @ wo^T + bo + x
    dim3 gH(HIDDEN / 128, MTOK / 128);
    gemm_h<1><<<gH, 256, SMGE>>>(attn, HIDDEN, rwo, HIDDEN, x1, HIDDEN, HIDDEN, bo, x, HIDDEN);

    // 5. LN2
    ln_k<<<MTOK / 8, 256>>>(x1, ln2g, ln2b, xn);

    // 6. h = gelu(xn @ w1 + b1)
    gemm_h<2><<<dim3(MLPH / 128, MTOK / 128), 256, SMGE>>>(
        xn, HIDDEN, w1t, HIDDEN, hm, MLPH, HIDDEN, b1, nullptr, 0);

    // 7. out = h @ w2 + b2 + x1
    gemm_h<1><<<gH, 256, SMGE>>>(hm, MLPH, w2t, MLPH, out, HIDDEN, MLPH, b2, x1, HIDDEN);
}